// round 2
// baseline (speedup 1.0000x reference)
#include <cuda_runtime.h>

// Problem constants
#define T_TOKENS 32768      // B*S
#define TM 32               // tokens per CTA
#define NTHREADS 512
#define DK 8                // d-chunk depth
#define BP 1036             // Bs pitch in floats (pad: conflict-free STS + 16B aligned)
#define AP 36               // As pitch in floats
#define SM_FLOATS (DK*BP + DK*AP + TM*1024 + 64 + 64 + 64)

// Output layout (float element offsets): quantized | indices | quant | avg_probs | x
#define OFF_Q     0
#define OFF_IDX   33554432
#define OFF_QUANT 33685504
#define OFF_AVG   67239936
#define OFF_X     100794368

static __device__ __forceinline__ unsigned long long pack2(float x) {
    unsigned long long r;
    asm("mov.b64 %0, {%1, %1};" : "=l"(r) : "f"(x));
    return r;
}
static __device__ __forceinline__ unsigned long long pack2b(float lo, float hi) {
    unsigned long long r;
    asm("mov.b64 %0, {%1, %2};" : "=l"(r) : "f"(lo), "f"(hi));
    return r;
}
// d = a * b + d on packed f32x2 (SASS FFMA2 — 2x scalar FFMA throughput)
static __device__ __forceinline__ void ffma2(unsigned long long& d,
                                             unsigned long long a,
                                             unsigned long long b) {
    asm("fma.rn.f32x2 %0, %1, %2, %0;" : "+l"(d) : "l"(a), "l"(b));
}
static __device__ __forceinline__ float lo32(unsigned long long v) {
    return __uint_as_float((unsigned)v);
}
static __device__ __forceinline__ float hi32(unsigned long long v) {
    return __uint_as_float((unsigned)(v >> 32));
}

__global__ __launch_bounds__(NTHREADS, 1)
void ahq_kernel(const float* __restrict__ x,
                const float* __restrict__ cb,
                const float* __restrict__ temp,
                float* __restrict__ out)
{
    extern __shared__ float sm[];
    float* Bs   = sm;                    // [DK][BP]  codebook chunk, d-major
    float* As   = Bs + DK * BP;          // [DK][AP]  x chunk (pre-scaled by 1/tau), d-major
    float* Pacc = As + DK * AP;          // [TM][1024] avg-probs accumulator
    float* redM = Pacc + TM * 1024;      // [32 tokens][2 halves]
    int*   redI = (int*)(redM + 64);
    float* redZ = (float*)(redI + 64);

    const int t      = threadIdx.x;
    const int tx     = t & 63;           // code-group axis (64)
    const int ty     = t >> 6;           // token-group axis (8)
    const int half   = tx >> 5;          // warp-half within the 64 threads of a token row
    const int token0 = blockIdx.x * TM;
    const float inv_tau = 1.0f / fmaxf(temp[0], 0.04f);

    // zero avg-probs accumulator
    for (int i = t; i < TM * 1024; i += NTHREADS) Pacc[i] = 0.0f;

    unsigned long long acc2[32];   // 64 fp32 accumulators as 32 packed pairs
    float4 rB[4];                  // codebook staging (16 floats)
    float4 rA;                     // x staging (threads 0..63)

    const int kbase = t >> 1;            // 0..255
    const int djB   = (t & 1) << 2;      // 0 or 4

    for (int l = 0; l < 4; ++l) {
        #pragma unroll
        for (int i = 0; i < 32; ++i) acc2[i] = 0ULL;

        auto ldg = [&](int d0) {
            const float* cbp = cb + (l << 18) + d0 + djB;   // l*1024*256
            #pragma unroll
            for (int p = 0; p < 4; ++p)
                rB[p] = *(const float4*)(cbp + (((p << 8) + kbase) << 8));
            if (t < 64) {
                int tt = t >> 1;
                int xi = ((token0 + tt) << 10) + (l << 8) + d0 + djB;
                rA = *(const float4*)(x + xi);
                *(float4*)(out + OFF_X + xi) = rA;   // fused x copy (each elem once)
            }
        };
        auto sts = [&]() {
            #pragma unroll
            for (int p = 0; p < 4; ++p) {
                int col = (p << 8) + kbase;
                Bs[(djB + 0) * BP + col] = rB[p].x;
                Bs[(djB + 1) * BP + col] = rB[p].y;
                Bs[(djB + 2) * BP + col] = rB[p].z;
                Bs[(djB + 3) * BP + col] = rB[p].w;
            }
            if (t < 64) {
                int tt = t >> 1;
                As[(djB + 0) * AP + tt] = rA.x * inv_tau;
                As[(djB + 1) * AP + tt] = rA.y * inv_tau;
                As[(djB + 2) * AP + tt] = rA.z * inv_tau;
                As[(djB + 3) * AP + tt] = rA.w * inv_tau;
            }
        };
        auto compute = [&]() {
            #pragma unroll
            for (int d = 0; d < DK; ++d) {
                float4 a4 = *(const float4*)(As + d * AP + (ty << 2));
                unsigned long long pa0 = pack2(a4.x);
                unsigned long long pa1 = pack2(a4.y);
                unsigned long long pa2 = pack2(a4.z);
                unsigned long long pa3 = pack2(a4.w);
                #pragma unroll
                for (int j = 0; j < 4; ++j) {
                    ulonglong2 bv = *(const ulonglong2*)(Bs + d * BP + (j << 8) + (tx << 2));
                    ffma2(acc2[0 * 8 + j * 2 + 0], pa0, bv.x);
                    ffma2(acc2[0 * 8 + j * 2 + 1], pa0, bv.y);
                    ffma2(acc2[1 * 8 + j * 2 + 0], pa1, bv.x);
                    ffma2(acc2[1 * 8 + j * 2 + 1], pa1, bv.y);
                    ffma2(acc2[2 * 8 + j * 2 + 0], pa2, bv.x);
                    ffma2(acc2[2 * 8 + j * 2 + 1], pa2, bv.y);
                    ffma2(acc2[3 * 8 + j * 2 + 0], pa3, bv.x);
                    ffma2(acc2[3 * 8 + j * 2 + 1], pa3, bv.y);
                }
            }
        };

        // software-pipelined chunk loop (register-staged prefetch of next chunk)
        ldg(0);
        __syncthreads();               // protect smem from previous layer's readers
        sts();
        __syncthreads();
        for (int c = 0; c < 32; ++c) {
            if (c + 1 < 32) ldg((c + 1) * DK);
            compute();
            __syncthreads();
            if (c + 1 < 32) { sts(); __syncthreads(); }
        }

        // ================= epilogue for layer l =================
        // 1) argmax (first-occurrence tie-break on smaller code index)
        float M[4]; int MI[4];
        #pragma unroll
        for (int tt = 0; tt < 4; ++tt) {
            float m = -3.4e38f; int mi = 0;
            #pragma unroll
            for (int h = 0; h < 8; ++h) {
                unsigned long long v = acc2[tt * 8 + h];
                float flo = lo32(v), fhi = hi32(v);
                int code = ((h >> 1) << 8) + (tx << 2) + ((h & 1) << 1);
                if (flo > m) { m = flo; mi = code; }
                if (fhi > m) { m = fhi; mi = code + 1; }
            }
            #pragma unroll
            for (int off = 16; off > 0; off >>= 1) {
                float om = __shfl_down_sync(0xffffffffu, m, off);
                int   oi = __shfl_down_sync(0xffffffffu, mi, off);
                if (om > m || (om == m && oi < mi)) { m = om; mi = oi; }
            }
            M[tt] = m; MI[tt] = mi;
        }
        if ((tx & 31) == 0) {
            #pragma unroll
            for (int tt = 0; tt < 4; ++tt) {
                redM[((((ty << 2) + tt) << 1)) + half] = M[tt];
                redI[((((ty << 2) + tt) << 1)) + half] = MI[tt];
            }
        }
        __syncthreads();
        #pragma unroll
        for (int tt = 0; tt < 4; ++tt) {
            int r = ((ty << 2) + tt) << 1;
            float m0 = redM[r], m1 = redM[r + 1];
            int   i0 = redI[r], i1 = redI[r + 1];
            if (m1 > m0 || (m1 == m0 && i1 < i0)) { M[tt] = m1; MI[tt] = i1; }
            else                                  { M[tt] = m0; MI[tt] = i0; }
        }
        // 2) exp + denominator (overwrite acc2 with exp values)
        #pragma unroll
        for (int tt = 0; tt < 4; ++tt) {
            float s = 0.0f;
            #pragma unroll
            for (int h = 0; h < 8; ++h) {
                unsigned long long v = acc2[tt * 8 + h];
                float elo = __expf(lo32(v) - M[tt]);
                float ehi = __expf(hi32(v) - M[tt]);
                s += elo + ehi;
                acc2[tt * 8 + h] = pack2b(elo, ehi);
            }
            #pragma unroll
            for (int off = 16; off > 0; off >>= 1)
                s += __shfl_down_sync(0xffffffffu, s, off);
            if ((tx & 31) == 0) redZ[((((ty << 2) + tt) << 1)) + half] = s;
        }
        __syncthreads();
        float Zq[4];
        #pragma unroll
        for (int tt = 0; tt < 4; ++tt) {
            int r = ((ty << 2) + tt) << 1;
            Zq[tt] = 0.25f / (redZ[r] + redZ[r + 1]);   // softmax norm * 1/L
        }
        // 3) accumulate avg probs in smem; write index + hard_q gather
        #pragma unroll
        for (int tt = 0; tt < 4; ++tt) {
            int token = token0 + (ty << 2) + tt;
            unsigned long long iz = pack2(Zq[tt]);
            unsigned long long* P2 = (unsigned long long*)(Pacc + (((ty << 2) + tt) << 10));
            #pragma unroll
            for (int j = 0; j < 4; ++j) {
                unsigned long long* pp = P2 + ((((j << 8) + (tx << 2))) >> 1);
                ulonglong2 pv = *(ulonglong2*)pp;
                ffma2(pv.x, acc2[tt * 8 + j * 2 + 0], iz);
                ffma2(pv.y, acc2[tt * 8 + j * 2 + 1], iz);
                *(ulonglong2*)pp = pv;
            }
            if (tx == 0) out[OFF_IDX + token * 4 + l] = (float)MI[tt];
            float4 q = *(const float4*)(cb + (((l << 10) + MI[tt]) << 8) + (tx << 2));
            int qi = token * 256 + (l << 6) + tx;          // float4 units
            ((float4*)out)[(OFF_Q     >> 2) + qi] = q;     // quantized
            ((float4*)out)[(OFF_QUANT >> 2) + qi] = q;     // quant (identical values)
        }
        __syncthreads();   // protect smem for next layer
    }

    // final avg_code_probs write
    #pragma unroll
    for (int tt = 0; tt < 4; ++tt) {
        int token = token0 + (ty << 2) + tt;
        const float4* Pp = (const float4*)(Pacc + (((ty << 2) + tt) << 10));
        #pragma unroll
        for (int j = 0; j < 4; ++j)
            ((float4*)out)[(OFF_AVG >> 2) + token * 256 + (j << 6) + tx] = Pp[(j << 6) + tx];
    }
}

extern "C" void kernel_launch(void* const* d_in, const int* in_sizes, int n_in,
                              void* d_out, int out_size)
{
    const float* x    = (const float*)d_in[0];
    const float* cb   = (const float*)d_in[1];
    const float* temp = (const float*)d_in[2];
    float* out = (float*)d_out;
    (void)in_sizes; (void)n_in; (void)out_size;

    size_t smem = SM_FLOATS * sizeof(float);   // ~166 KB (< 227 KB sm_103a cap)
    cudaFuncSetAttribute(ahq_kernel, cudaFuncAttributeMaxDynamicSharedMemorySize, (int)smem);
    ahq_kernel<<<T_TOKENS / TM, NTHREADS, smem>>>(x, cb, temp, out);
}